// round 3
// baseline (speedup 1.0000x reference)
#include <cuda_runtime.h>

#define NQ 12288
#define DQK 8
#define DV 64
#define SPLIT 3
#define TK 32
#define QT 128          // queries per block (attn)
#define ATHREADS 256
#define QBLK 128        // qkv kernel block

// ---- scratch (no cudaMalloc allowed) ----
__device__ __align__(16) float g_Q[NQ * DQK];
__device__ __align__(16) float g_K[NQ * DQK];
__device__ __align__(16) float g_V[NQ * DV];
__device__ __align__(16) float g_num[SPLIT * NQ * DV];
__device__ __align__(16) float g_den[SPLIT * NQ];

__device__ __forceinline__ float ex2f(float x) {
    float r;
    asm("ex2.approx.ftz.f32 %0, %1;" : "=f"(r) : "f"(x));
    return r;
}
// packed fp32x2 FMA: a += v * e
__device__ __forceinline__ void fma2(unsigned long long& a, unsigned long long v,
                                     unsigned long long e) {
    asm("fma.rn.f32x2 %0, %1, %2, %0;" : "+l"(a) : "l"(v), "l"(e));
}
__device__ __forceinline__ unsigned long long dup2(float x) {
    unsigned long long r;
    asm("mov.b64 %0, {%1, %1};" : "=l"(r) : "f"(x));
    return r;
}
__device__ __forceinline__ unsigned long long pack2(float lo, float hi) {
    unsigned long long r;
    asm("mov.b64 %0, {%1, %2};" : "=l"(r) : "f"(lo), "f"(hi));
    return r;
}
__device__ __forceinline__ void unpack2(unsigned long long v, float& a, float& b) {
    asm("mov.b64 {%0, %1}, %2;" : "=f"(a), "=f"(b) : "l"(v));
}

__device__ __forceinline__ void acc16(float h[16], float x, const float4* wrow) {
    float4 a = wrow[0], b = wrow[1], c = wrow[2], d = wrow[3];
    h[0]  = fmaf(x, a.x, h[0]);  h[1]  = fmaf(x, a.y, h[1]);
    h[2]  = fmaf(x, a.z, h[2]);  h[3]  = fmaf(x, a.w, h[3]);
    h[4]  = fmaf(x, b.x, h[4]);  h[5]  = fmaf(x, b.y, h[5]);
    h[6]  = fmaf(x, b.z, h[6]);  h[7]  = fmaf(x, b.w, h[7]);
    h[8]  = fmaf(x, c.x, h[8]);  h[9]  = fmaf(x, c.y, h[9]);
    h[10] = fmaf(x, c.z, h[10]); h[11] = fmaf(x, c.w, h[11]);
    h[12] = fmaf(x, d.x, h[12]); h[13] = fmaf(x, d.y, h[13]);
    h[14] = fmaf(x, d.z, h[14]); h[15] = fmaf(x, d.w, h[15]);
}

// ---------------------------------------------------------------------------
// Kernel A: per-row MLP -> h, then Q (pre-scaled by log2(e)/sqrt(8)), K, V
// ---------------------------------------------------------------------------
__global__ __launch_bounds__(QBLK) void qkv_kernel(
    const float* __restrict__ xm, const float* __restrict__ xd,
    const float* __restrict__ W1, const float* __restrict__ W2,
    const float* __restrict__ Wq, const float* __restrict__ Wk,
    const float* __restrict__ Wv) {
    __shared__ __align__(16) float4 W1s[192 * 4];
    __shared__ __align__(16) float4 W2s[16 * 4];
    __shared__ float Wqs[16 * 8];
    __shared__ float Wks[16 * 8];
    __shared__ __align__(16) float4 Wvs[16 * 16];

    int tid = threadIdx.x;
    for (int i = tid; i < 192 * 4; i += QBLK) W1s[i] = ((const float4*)W1)[i];
    for (int i = tid; i < 16 * 4; i += QBLK) W2s[i] = ((const float4*)W2)[i];
    for (int i = tid; i < 128; i += QBLK) { Wqs[i] = Wq[i]; Wks[i] = Wk[i]; }
    for (int i = tid; i < 16 * 16; i += QBLK) Wvs[i] = ((const float4*)Wv)[i];
    __syncthreads();

    int r = blockIdx.x * QBLK + tid;

    float h1[16];
#pragma unroll
    for (int j = 0; j < 16; j++) h1[j] = 0.f;

    const float4* xm4 = (const float4*)(xm + (size_t)r * 64);
#pragma unroll
    for (int b = 0; b < 16; b++) {
        float4 xv = xm4[b];
        int k = b * 4;
        acc16(h1, xv.x, &W1s[(k + 0) * 4]);
        acc16(h1, xv.y, &W1s[(k + 1) * 4]);
        acc16(h1, xv.z, &W1s[(k + 2) * 4]);
        acc16(h1, xv.w, &W1s[(k + 3) * 4]);
    }
    const float4* xd4 = (const float4*)(xd + (size_t)r * 128);
#pragma unroll
    for (int b = 0; b < 32; b++) {
        float4 xv = xd4[b];
        int k = 64 + b * 4;
        acc16(h1, xv.x, &W1s[(k + 0) * 4]);
        acc16(h1, xv.y, &W1s[(k + 1) * 4]);
        acc16(h1, xv.z, &W1s[(k + 2) * 4]);
        acc16(h1, xv.w, &W1s[(k + 3) * 4]);
    }
#pragma unroll
    for (int j = 0; j < 16; j++) h1[j] = fmaxf(h1[j], 0.f);

    float h2[16];
#pragma unroll
    for (int j = 0; j < 16; j++) h2[j] = 0.f;
#pragma unroll
    for (int k = 0; k < 16; k++) acc16(h2, h1[k], &W2s[k * 4]);
#pragma unroll
    for (int j = 0; j < 16; j++) h2[j] = fmaxf(h2[j], 0.f);

    float qv[8], kv[8];
#pragma unroll
    for (int j = 0; j < 8; j++) { qv[j] = 0.f; kv[j] = 0.f; }
#pragma unroll
    for (int k = 0; k < 16; k++) {
        float hk = h2[k];
#pragma unroll
        for (int j = 0; j < 8; j++) {
            qv[j] = fmaf(hk, Wqs[k * 8 + j], qv[j]);
            kv[j] = fmaf(hk, Wks[k * 8 + j], kv[j]);
        }
    }
    const float QS = (float)(1.4426950408889634 / 2.8284271247461903);  // log2(e)/sqrt(8)
#pragma unroll
    for (int j = 0; j < 8; j++) qv[j] *= QS;

    ((float4*)(g_Q + (size_t)r * 8))[0] = make_float4(qv[0], qv[1], qv[2], qv[3]);
    ((float4*)(g_Q + (size_t)r * 8))[1] = make_float4(qv[4], qv[5], qv[6], qv[7]);
    ((float4*)(g_K + (size_t)r * 8))[0] = make_float4(kv[0], kv[1], kv[2], kv[3]);
    ((float4*)(g_K + (size_t)r * 8))[1] = make_float4(kv[4], kv[5], kv[6], kv[7]);

    float v[64];
#pragma unroll
    for (int c = 0; c < 64; c++) v[c] = 0.f;
#pragma unroll
    for (int k = 0; k < 16; k++) {
        float hk = h2[k];
        const float4* wr = &Wvs[k * 16];
#pragma unroll
        for (int c = 0; c < 16; c++) {
            float4 w = wr[c];
            v[4 * c + 0] = fmaf(hk, w.x, v[4 * c + 0]);
            v[4 * c + 1] = fmaf(hk, w.y, v[4 * c + 1]);
            v[4 * c + 2] = fmaf(hk, w.z, v[4 * c + 2]);
            v[4 * c + 3] = fmaf(hk, w.w, v[4 * c + 3]);
        }
    }
    float4* vout = (float4*)(g_V + (size_t)r * 64);
#pragma unroll
    for (int c = 0; c < 16; c++)
        vout[c] = make_float4(v[4 * c + 0], v[4 * c + 1], v[4 * c + 2], v[4 * c + 3]);
}

// ---------------------------------------------------------------------------
// Kernel B: tiled GEMM attention. Block = 128 queries x 64 cols, 256 threads.
// Per tile of TK=32 keys: build exp-score tile e[TK][128] in SMEM, then
// register-blocked e^T @ V with 8q x 4c micro-tiles (packed f32x2 FMA).
// No max-subtraction (scores O(1)); split-K partials combine by addition.
// ---------------------------------------------------------------------------
__global__ __launch_bounds__(ATHREADS, 2) void attn_kernel() {
    __shared__ __align__(16) float e_s[TK * 128];              // [k][q]
    __shared__ __align__(16) float Vs[TK * 68];                // [k][c] pad 68
    __shared__ __align__(16) unsigned long long Kbs[8 * TK];   // [d][k] dup pairs
    __shared__ float2 dens[256];                               // [qp][kg]

    const int tid = threadIdx.x;
    const int qbase = blockIdx.x * QT;
    const int kbase = blockIdx.y * (NQ / SPLIT);
    const int KPB = NQ / SPLIT;

    // PV mapping: 8q x 4c micro-tile
    const int qg = tid >> 4;        // 0..15  -> queries qg*8..+7
    const int cg = tid & 15;        // 0..15  -> cols cg*4..+3
    // score mapping: 2 queries x 8 keys
    const int qp = tid & 63;        // queries 2qp, 2qp+1
    const int kg = tid >> 6;        // keys kg*8..+7 of tile

    // Q for score phase, packed (q0,q1) per dim
    unsigned long long q2[8];
    {
        const float4* Q4 = (const float4*)(g_Q + (size_t)(qbase + 2 * qp) * 8);
        float4 a0 = Q4[0], a1 = Q4[1], b0 = Q4[2], b1 = Q4[3];
        q2[0] = pack2(a0.x, b0.x); q2[1] = pack2(a0.y, b0.y);
        q2[2] = pack2(a0.z, b0.z); q2[3] = pack2(a0.w, b0.w);
        q2[4] = pack2(a1.x, b1.x); q2[5] = pack2(a1.y, b1.y);
        q2[6] = pack2(a1.z, b1.z); q2[7] = pack2(a1.w, b1.w);
    }

    unsigned long long acc[16];
#pragma unroll
    for (int i = 0; i < 16; i++) acc[i] = 0ull;
    float den0 = 0.f, den1 = 0.f;

    const int kload = tid >> 3;     // 0..31
    const int dload = tid & 7;      // 0..7

    for (int t = 0; t < KPB; t += TK) {
        // ---- load K (dup-packed, transposed) and V tile ----
        Kbs[dload * TK + kload] = dup2(g_K[(size_t)(kbase + t + kload) * 8 + dload]);
        {
            const float4* Vg = (const float4*)(g_V + (size_t)(kbase + t) * 64);
#pragma unroll
            for (int i = tid; i < TK * 16; i += ATHREADS) {
                int row = i >> 4, c4 = i & 15;
                *(float4*)&Vs[row * 68 + c4 * 4] = Vg[i];
            }
        }
        __syncthreads();

        // ---- score phase: e[k][q] for 8 keys x 2 queries per thread ----
        {
            unsigned long long s2[8];
#pragma unroll
            for (int kk = 0; kk < 8; kk++) s2[kk] = 0ull;
#pragma unroll
            for (int d = 0; d < 8; d++) {
                const unsigned long long* kb = &Kbs[d * TK + kg * 8];
#pragma unroll
                for (int kk = 0; kk < 8; kk++) fma2(s2[kk], q2[d], kb[kk]);
            }
#pragma unroll
            for (int kk = 0; kk < 8; kk++) {
                float a, b;
                unpack2(s2[kk], a, b);
                float e0 = ex2f(a), e1 = ex2f(b);
                den0 += e0; den1 += e1;
                *(float2*)&e_s[(kg * 8 + kk) * 128 + 2 * qp] = make_float2(e0, e1);
            }
        }
        __syncthreads();

        // ---- PV phase: acc[8q x 4c] += e^T @ V ----
        const float* ep = &e_s[qg * 8];
        const float* vp = &Vs[cg * 4];
#pragma unroll 4
        for (int k = 0; k < TK; k++) {
            ulonglong2 eA = *(const ulonglong2*)(ep + k * 128);
            ulonglong2 eB = *(const ulonglong2*)(ep + k * 128 + 4);
            float4 v = *(const float4*)(vp + k * 68);
            unsigned long long v0 = dup2(v.x), v1 = dup2(v.y),
                               v2 = dup2(v.z), v3 = dup2(v.w);
            fma2(acc[0],  eA.x, v0); fma2(acc[1],  eA.x, v1);
            fma2(acc[2],  eA.x, v2); fma2(acc[3],  eA.x, v3);
            fma2(acc[4],  eA.y, v0); fma2(acc[5],  eA.y, v1);
            fma2(acc[6],  eA.y, v2); fma2(acc[7],  eA.y, v3);
            fma2(acc[8],  eB.x, v0); fma2(acc[9],  eB.x, v1);
            fma2(acc[10], eB.x, v2); fma2(acc[11], eB.x, v3);
            fma2(acc[12], eB.y, v0); fma2(acc[13], eB.y, v1);
            fma2(acc[14], eB.y, v2); fma2(acc[15], eB.y, v3);
        }
        __syncthreads();
    }

    // ---- write numerator partials ----
    {
        float* np = g_num + ((size_t)blockIdx.y * NQ + qbase + qg * 8) * 64 + cg * 4;
#pragma unroll
        for (int p = 0; p < 4; p++) {
            float l0, h0, l1, h1, l2, h2, l3, h3;
            unpack2(acc[p * 4 + 0], l0, h0);
            unpack2(acc[p * 4 + 1], l1, h1);
            unpack2(acc[p * 4 + 2], l2, h2);
            unpack2(acc[p * 4 + 3], l3, h3);
            *(float4*)(np + (size_t)(2 * p) * 64)     = make_float4(l0, l1, l2, l3);
            *(float4*)(np + (size_t)(2 * p + 1) * 64) = make_float4(h0, h1, h2, h3);
        }
    }

    // ---- reduce denominators ----
    dens[qp * 4 + kg] = make_float2(den0, den1);
    __syncthreads();
    if (tid < QT) {
        int q = tid;
        int base = (q >> 1) * 4;
        float s = 0.f;
#pragma unroll
        for (int g = 0; g < 4; g++) {
            float2 d2 = dens[base + g];
            s += (q & 1) ? d2.y : d2.x;
        }
        g_den[blockIdx.y * NQ + qbase + q] = s;
    }
}

// ---------------------------------------------------------------------------
// Kernel C: combine splits + divide
// ---------------------------------------------------------------------------
__global__ void combine_kernel(float* __restrict__ out) {
    int i = blockIdx.x * blockDim.x + threadIdx.x;
    if (i >= NQ * DV) return;
    int r = i >> 6;
    float s = 0.f, d = 0.f;
#pragma unroll
    for (int p = 0; p < SPLIT; p++) {
        s += g_num[(size_t)p * NQ * DV + i];
        d += g_den[p * NQ + r];
    }
    out[i] = s / d;
}

extern "C" void kernel_launch(void* const* d_in, const int* in_sizes, int n_in,
                              void* d_out, int out_size) {
    const float* xm = (const float*)d_in[0];
    const float* xd = (const float*)d_in[1];
    const float* W1 = (const float*)d_in[3];
    const float* W2 = (const float*)d_in[4];
    const float* Wq = (const float*)d_in[5];
    const float* Wk = (const float*)d_in[6];
    const float* Wv = (const float*)d_in[7];

    qkv_kernel<<<NQ / QBLK, QBLK>>>(xm, xd, W1, W2, Wq, Wk, Wv);
    attn_kernel<<<dim3(NQ / QT, SPLIT), ATHREADS>>>();
    combine_kernel<<<(NQ * DV + 255) / 256, 256>>>((float*)d_out);
}

// round 5
// speedup vs baseline: 5.3020x; 5.3020x over previous
#include <cuda_runtime.h>
#include <cuda_bf16.h>
#include <cstdint>

#define NQ 12288
#define SPLIT 3
#define KPB (NQ / SPLIT)   // 4096
#define KT 64
#define NT (KPB / KT)      // 64 tiles per CTA
#define QT 128
#define QBLK 128
#define VROW 144           // padded SMEM row stride for V^T (bytes)

// ---- scratch (no cudaMalloc allowed) ----
__device__ __align__(16) unsigned char g_Qhi[NQ * 16];            // 8 bf16 (scaled q, hi)
__device__ __align__(16) unsigned char g_Qlo[NQ * 16];            // 8 bf16 (residual)
__device__ __align__(16) unsigned char g_Kd[NQ * 16];             // 8 bf16 per key
__device__ __align__(16) unsigned char g_Vt[(NQ / 64) * 8192];    // [tile][c 0..63][key 0..63] bf16
__device__ __align__(16) float g_num[SPLIT * NQ * 64];
__device__ __align__(16) float g_den[SPLIT * NQ];

// ============ helpers ============
__device__ __forceinline__ float ex2f(float x) {
    float r; asm("ex2.approx.ftz.f32 %0, %1;" : "=f"(r) : "f"(x)); return r;
}
// pack (lo, hi) floats -> bf16x2 (lo in low half)
__device__ __forceinline__ uint32_t pack_bf2(float lo, float hi) {
    uint32_t r;
    asm("cvt.rn.bf16x2.f32 %0, %1, %2;" : "=r"(r) : "f"(hi), "f"(lo));
    return r;
}
__device__ __forceinline__ void cp16(uint32_t dst, const void* src) {
    asm volatile("cp.async.ca.shared.global [%0], [%1], 16;" :: "r"(dst), "l"(src) : "memory");
}
#define CP_COMMIT() asm volatile("cp.async.commit_group;" ::: "memory")
#define CP_WAIT0()  asm volatile("cp.async.wait_group 0;" ::: "memory")

__device__ __forceinline__ uint32_t smem_u32(const void* p) {
    uint32_t a;
    asm("{ .reg .u64 t; cvta.to.shared.u64 t, %1; cvt.u32.u64 %0, t; }" : "=r"(a) : "l"(p));
    return a;
}
// D += A(bf16 m16k16) * B(bf16 k16n8), f32 accum
__device__ __forceinline__ void mma_bf16(float d[4], uint32_t a0, uint32_t a1, uint32_t a2,
                                         uint32_t a3, uint32_t b0, uint32_t b1) {
    asm volatile("mma.sync.aligned.m16n8k16.row.col.f32.bf16.bf16.f32 "
                 "{%0,%1,%2,%3}, {%4,%5,%6,%7}, {%8,%9}, {%0,%1,%2,%3};"
                 : "+f"(d[0]), "+f"(d[1]), "+f"(d[2]), "+f"(d[3])
                 : "r"(a0), "r"(a1), "r"(a2), "r"(a3), "r"(b0), "r"(b1));
}

__device__ __forceinline__ void acc16(float h[16], float x, const float4* wrow) {
    float4 a = wrow[0], b = wrow[1], c = wrow[2], d = wrow[3];
    h[0] = fmaf(x, a.x, h[0]);  h[1] = fmaf(x, a.y, h[1]);
    h[2] = fmaf(x, a.z, h[2]);  h[3] = fmaf(x, a.w, h[3]);
    h[4] = fmaf(x, b.x, h[4]);  h[5] = fmaf(x, b.y, h[5]);
    h[6] = fmaf(x, b.z, h[6]);  h[7] = fmaf(x, b.w, h[7]);
    h[8] = fmaf(x, c.x, h[8]);  h[9] = fmaf(x, c.y, h[9]);
    h[10] = fmaf(x, c.z, h[10]); h[11] = fmaf(x, c.w, h[11]);
    h[12] = fmaf(x, d.x, h[12]); h[13] = fmaf(x, d.y, h[13]);
    h[14] = fmaf(x, d.z, h[14]); h[15] = fmaf(x, d.w, h[15]);
}

// ---------------------------------------------------------------------------
// Kernel A: MLP -> Q(hi/lo bf16, pre-scaled), K(bf16), V^T bf16 tile images
// ---------------------------------------------------------------------------
__global__ __launch_bounds__(QBLK) void qkv_kernel(
    const float* __restrict__ xm, const float* __restrict__ xd,
    const float* __restrict__ W1, const float* __restrict__ W2,
    const float* __restrict__ Wq, const float* __restrict__ Wk,
    const float* __restrict__ Wv) {
    __shared__ __align__(16) float4 W1s[192 * 4];
    __shared__ __align__(16) float4 W2s[16 * 4];
    __shared__ float Wqs[16 * 8];
    __shared__ float Wks[16 * 8];
    __shared__ __align__(16) float4 Wvs[16 * 16];
    __shared__ uint16_t vS[128 * 66];   // staged V bf16, padded rows

    int tid = threadIdx.x;
    for (int i = tid; i < 192 * 4; i += QBLK) W1s[i] = ((const float4*)W1)[i];
    for (int i = tid; i < 16 * 4; i += QBLK) W2s[i] = ((const float4*)W2)[i];
    for (int i = tid; i < 128; i += QBLK) { Wqs[i] = Wq[i]; Wks[i] = Wk[i]; }
    for (int i = tid; i < 16 * 16; i += QBLK) Wvs[i] = ((const float4*)Wv)[i];
    __syncthreads();

    int r = blockIdx.x * QBLK + tid;

    float h1[16];
#pragma unroll
    for (int j = 0; j < 16; j++) h1[j] = 0.f;
    const float4* xm4 = (const float4*)(xm + (size_t)r * 64);
#pragma unroll
    for (int b = 0; b < 16; b++) {
        float4 xv = xm4[b]; int k = b * 4;
        acc16(h1, xv.x, &W1s[(k + 0) * 4]); acc16(h1, xv.y, &W1s[(k + 1) * 4]);
        acc16(h1, xv.z, &W1s[(k + 2) * 4]); acc16(h1, xv.w, &W1s[(k + 3) * 4]);
    }
    const float4* xd4 = (const float4*)(xd + (size_t)r * 128);
#pragma unroll
    for (int b = 0; b < 32; b++) {
        float4 xv = xd4[b]; int k = 64 + b * 4;
        acc16(h1, xv.x, &W1s[(k + 0) * 4]); acc16(h1, xv.y, &W1s[(k + 1) * 4]);
        acc16(h1, xv.z, &W1s[(k + 2) * 4]); acc16(h1, xv.w, &W1s[(k + 3) * 4]);
    }
#pragma unroll
    for (int j = 0; j < 16; j++) h1[j] = fmaxf(h1[j], 0.f);

    float h2[16];
#pragma unroll
    for (int j = 0; j < 16; j++) h2[j] = 0.f;
#pragma unroll
    for (int k = 0; k < 16; k++) acc16(h2, h1[k], &W2s[k * 4]);
#pragma unroll
    for (int j = 0; j < 16; j++) h2[j] = fmaxf(h2[j], 0.f);

    float qv[8], kv[8];
#pragma unroll
    for (int j = 0; j < 8; j++) { qv[j] = 0.f; kv[j] = 0.f; }
#pragma unroll
    for (int k = 0; k < 16; k++) {
        float hk = h2[k];
#pragma unroll
        for (int j = 0; j < 8; j++) {
            qv[j] = fmaf(hk, Wqs[k * 8 + j], qv[j]);
            kv[j] = fmaf(hk, Wks[k * 8 + j], kv[j]);
        }
    }
    const float QS = (float)(1.4426950408889634 / 2.8284271247461903);  // log2(e)/sqrt(8)

    {   // Q hi/lo bf16
        uint16_t hi[8], lo[8];
#pragma unroll
        for (int j = 0; j < 8; j++) {
            float q = qv[j] * QS;
            __nv_bfloat16 h = __float2bfloat16(q);
            float res = q - __bfloat162float(h);
            __nv_bfloat16 l = __float2bfloat16(res);
            hi[j] = *(uint16_t*)&h; lo[j] = *(uint16_t*)&l;
        }
        *(uint4*)(g_Qhi + (size_t)r * 16) = *(uint4*)hi;
        *(uint4*)(g_Qlo + (size_t)r * 16) = *(uint4*)lo;
    }
    {   // K bf16
        uint16_t kb[8];
#pragma unroll
        for (int j = 0; j < 8; j++) {
            __nv_bfloat16 b = __float2bfloat16(kv[j]);
            kb[j] = *(uint16_t*)&b;
        }
        *(uint4*)(g_Kd + (size_t)r * 16) = *(uint4*)kb;
    }

    // V -> bf16, stage in SMEM
    {
        float v[64];
#pragma unroll
        for (int c = 0; c < 64; c++) v[c] = 0.f;
#pragma unroll
        for (int k = 0; k < 16; k++) {
            float hk = h2[k];
            const float4* wr = &Wvs[k * 16];
#pragma unroll
            for (int c = 0; c < 16; c++) {
                float4 w = wr[c];
                v[4 * c + 0] = fmaf(hk, w.x, v[4 * c + 0]);
                v[4 * c + 1] = fmaf(hk, w.y, v[4 * c + 1]);
                v[4 * c + 2] = fmaf(hk, w.z, v[4 * c + 2]);
                v[4 * c + 3] = fmaf(hk, w.w, v[4 * c + 3]);
            }
        }
#pragma unroll
        for (int c = 0; c < 64; c++) {
            __nv_bfloat16 b = __float2bfloat16(v[c]);
            vS[tid * 66 + c] = *(uint16_t*)&b;
        }
    }
    __syncthreads();

    // transposed coalesced write: thread -> one (tile, col) row of 64 keys
    {
        int tt = tid >> 6, c = tid & 63;
        unsigned char* dst = g_Vt + (size_t)(blockIdx.x * 2 + tt) * 8192 + (size_t)c * 128;
#pragma unroll
        for (int seg = 0; seg < 8; seg++) {
            uint16_t tmp[8];
#pragma unroll
            for (int u = 0; u < 8; u++)
                tmp[u] = vS[(tt * 64 + seg * 8 + u) * 66 + c];
            *(uint4*)(dst + seg * 16) = *(uint4*)tmp;
        }
    }
}

// ---------------------------------------------------------------------------
// Kernel B: mma.sync bf16 flash attention. CTA = 128 queries, 8 warps.
// ---------------------------------------------------------------------------
__device__ __forceinline__ void prefetch_tile(uint32_t sKb, uint32_t sVb, int tid,
                                              const unsigned char* kptr,
                                              const unsigned char* vptr) {
    if (tid < 64) cp16(sKb + tid * 16, kptr + tid * 16);
    int r0 = tid >> 3, s0 = tid & 7;
    cp16(sVb + r0 * VROW + s0 * 16, vptr + r0 * 128 + s0 * 16);
    int i1 = tid + 256;
    int r1 = i1 >> 3, s1 = i1 & 7;
    cp16(sVb + r1 * VROW + s1 * 16, vptr + r1 * 128 + s1 * 16);
    CP_COMMIT();
}

__global__ __launch_bounds__(256, 2) void attn_kernel() {
    __shared__ __align__(16) unsigned char sK[2][1024];        // [key][8 bf16]
    __shared__ __align__(16) unsigned char sV[2][64 * VROW];   // [col][64 keys bf16], padded

    const int tid = threadIdx.x;
    const int wid = tid >> 5, lane = tid & 31;
    const int gr = lane >> 2, tig = lane & 3;
    const int qbase = blockIdx.x * QT;
    const int kbase = blockIdx.y * KPB;
    const int tile0 = kbase >> 6;
    const int m0 = qbase + wid * 16 + gr;

    // Q A-fragments (persist across tiles)
    const uint32_t qa0 = *(const uint32_t*)(g_Qhi + (size_t)m0 * 16 + 4 * tig);
    const uint32_t qa1 = *(const uint32_t*)(g_Qhi + (size_t)(m0 + 8) * 16 + 4 * tig);
    const uint32_t qa2 = *(const uint32_t*)(g_Qlo + (size_t)m0 * 16 + 4 * tig);
    const uint32_t qa3 = *(const uint32_t*)(g_Qlo + (size_t)(m0 + 8) * 16 + 4 * tig);

    float o[8][4];
#pragma unroll
    for (int i = 0; i < 8; i++)
#pragma unroll
        for (int j = 0; j < 4; j++) o[i][j] = 0.f;
    float den0 = 0.f, den1 = 0.f;

    const uint32_t sKb0 = smem_u32(sK[0]), sKb1 = smem_u32(sK[1]);
    const uint32_t sVb0 = smem_u32(sV[0]), sVb1 = smem_u32(sV[1]);

    prefetch_tile(sKb0, sVb0, tid, g_Kd + (size_t)kbase * 16, g_Vt + (size_t)tile0 * 8192);

    for (int t = 0; t < NT; t++) {
        CP_WAIT0();
        __syncthreads();
        if (t + 1 < NT) {
            int st = (t + 1) & 1;
            prefetch_tile(st ? sKb1 : sKb0, st ? sVb1 : sVb0, tid,
                          g_Kd + (size_t)(kbase + (t + 1) * 64) * 16,
                          g_Vt + (size_t)(tile0 + t + 1) * 8192);
        }
        const unsigned char* Ks = sK[t & 1];
        const unsigned char* Vs = sV[t & 1];

#pragma unroll
        for (int kc = 0; kc < 4; kc++) {
            // QK^T: n-blocks 2kc, 2kc+1 (keys 16kc..16kc+15)
            float s0[4] = {0.f, 0.f, 0.f, 0.f};
            float s1[4] = {0.f, 0.f, 0.f, 0.f};
            uint32_t kb0 = *(const uint32_t*)(Ks + (16 * kc + gr) * 16 + 4 * tig);
            uint32_t kb1 = *(const uint32_t*)(Ks + (16 * kc + 8 + gr) * 16 + 4 * tig);
            mma_bf16(s0, qa0, qa1, qa2, qa3, kb0, kb0);
            mma_bf16(s1, qa0, qa1, qa2, qa3, kb1, kb1);

            // exp + denominator + pack into A-fragments for PV
            float e00 = ex2f(s0[0]), e01 = ex2f(s0[1]), e02 = ex2f(s0[2]), e03 = ex2f(s0[3]);
            float e10 = ex2f(s1[0]), e11 = ex2f(s1[1]), e12 = ex2f(s1[2]), e13 = ex2f(s1[3]);
            den0 += (e00 + e01) + (e10 + e11);
            den1 += (e02 + e03) + (e12 + e13);
            uint32_t pa0 = pack_bf2(e00, e01);
            uint32_t pa1 = pack_bf2(e02, e03);
            uint32_t pa2 = pack_bf2(e10, e11);
            uint32_t pa3 = pack_bf2(e12, e13);

            // PV: 8 n-blocks of output cols
            const unsigned char* vb = Vs + gr * VROW + 32 * kc + 4 * tig;
#pragma unroll
            for (int nb = 0; nb < 8; nb++) {
                uint32_t vb0 = *(const uint32_t*)(vb + nb * 8 * VROW);
                uint32_t vb1 = *(const uint32_t*)(vb + nb * 8 * VROW + 16);
                mma_bf16(o[nb], pa0, pa1, pa2, pa3, vb0, vb1);
            }
        }
        __syncthreads();
    }

    // denominator quad-reduce + write
    den0 += __shfl_xor_sync(0xffffffffu, den0, 1);
    den0 += __shfl_xor_sync(0xffffffffu, den0, 2);
    den1 += __shfl_xor_sync(0xffffffffu, den1, 1);
    den1 += __shfl_xor_sync(0xffffffffu, den1, 2);
    if (tig == 0) {
        g_den[blockIdx.y * NQ + m0] = den0;
        g_den[blockIdx.y * NQ + m0 + 8] = den1;
    }

    // numerator write
    float* np0 = g_num + ((size_t)blockIdx.y * NQ + m0) * 64;
    float* np1 = np0 + 8 * 64;
#pragma unroll
    for (int nb = 0; nb < 8; nb++) {
        *(float2*)(np0 + 8 * nb + 2 * tig) = make_float2(o[nb][0], o[nb][1]);
        *(float2*)(np1 + 8 * nb + 2 * tig) = make_float2(o[nb][2], o[nb][3]);
    }
}

// ---------------------------------------------------------------------------
// Kernel C: combine splits + divide
// ---------------------------------------------------------------------------
__global__ void combine_kernel(float* __restrict__ out) {
    int i = blockIdx.x * blockDim.x + threadIdx.x;
    if (i >= NQ * 64) return;
    int r = i >> 6;
    float s = 0.f, d = 0.f;
#pragma unroll
    for (int p = 0; p < SPLIT; p++) {
        s += g_num[(size_t)p * NQ * 64 + i];
        d += g_den[p * NQ + r];
    }
    out[i] = s / d;
}

extern "C" void kernel_launch(void* const* d_in, const int* in_sizes, int n_in,
                              void* d_out, int out_size) {
    const float* xm = (const float*)d_in[0];
    const float* xd = (const float*)d_in[1];
    const float* W1 = (const float*)d_in[3];
    const float* W2 = (const float*)d_in[4];
    const float* Wq = (const float*)d_in[5];
    const float* Wk = (const float*)d_in[6];
    const float* Wv = (const float*)d_in[7];

    qkv_kernel<<<NQ / QBLK, QBLK>>>(xm, xd, W1, W2, Wq, Wk, Wv);
    attn_kernel<<<dim3(NQ / QT, SPLIT), 256>>>();
    combine_kernel<<<(NQ * 64 + 255) / 256, 256>>>((float*)d_out);
}